// round 5
// baseline (speedup 1.0000x reference)
#include <cuda_runtime.h>
#include <cuda_bf16.h>
#include <cuda_fp16.h>
#include <math.h>
#include <cstdint>

// Problem constants
#define HDIM 1024
#define KDIM 2048
#define GATES 5
#define BSZ 32
#define STEPS 128
#define AMB 32
#define STARTI 256
#define CHART_LEN 384
#define NROWS (STEPS * BSZ * AMB)   // 131072
#define NX (BSZ * STARTI)           // 8192 distinct h-vectors
#define PPW (2 * GATES * HDIM)      // 10240 PP cols

// Static device scratch
__device__ float g_p[(size_t)NX * PPW];
__device__ __nv_bfloat16 g_a0[(size_t)NX * HDIM];
__device__ __nv_bfloat16 g_a1[(size_t)NX * HDIM];
__device__ __nv_bfloat16 g_u0[(size_t)PPW * HDIM];
__device__ __nv_bfloat16 g_u1[(size_t)PPW * HDIM];
__device__ float g_unorm;

__device__ __forceinline__ float sigmoidf_(float x) {
    return 1.0f / (1.0f + __expf(-x));
}
__device__ __forceinline__ uint32_t smem_u32(const void* p) {
    uint32_t a;
    asm("{ .reg .u64 t; cvta.to.shared.u64 t, %1; cvt.u32.u64 %0, t; }" : "=r"(a) : "l"(p));
    return a;
}
#define LDMATRIX_X4(r, addr) \
    asm volatile("ldmatrix.sync.aligned.m8n8.x4.shared.b16 {%0,%1,%2,%3}, [%4];" \
        : "=r"((r)[0]), "=r"((r)[1]), "=r"((r)[2]), "=r"((r)[3]) : "r"(addr))
__device__ __forceinline__ void mma16816(float* d, const uint32_t* a, const uint32_t* b) {
    asm volatile(
        "mma.sync.aligned.m16n8k16.row.col.f32.bf16.bf16.f32 "
        "{%0,%1,%2,%3}, {%4,%5,%6,%7}, {%8,%9}, {%0,%1,%2,%3};"
        : "+f"(d[0]), "+f"(d[1]), "+f"(d[2]), "+f"(d[3])
        : "r"(a[0]), "r"(a[1]), "r"(a[2]), "r"(a[3]), "r"(b[0]), "r"(b[1]));
}
__device__ __forceinline__ void cpasync16(uint32_t dst, const __nv_bfloat16* src) {
    asm volatile("cp.async.cg.shared.global [%0], [%1], 16;"
        :: "r"(dst), "l"((size_t)__cvta_generic_to_global(src)));
}
#define CP_COMMIT() asm volatile("cp.async.commit_group;" ::: "memory")
#define CP_WAIT1()  asm volatile("cp.async.wait_group 1;" ::: "memory")
#define CP_WAIT0()  asm volatile("cp.async.wait_group 0;" ::: "memory")

// ---------------------------------------------------------------------------
// K1: copy chart rows [0,256)
// ---------------------------------------------------------------------------
__global__ __launch_bounds__(256) void copy_kernel(const float4* __restrict__ src,
                                                   float4* __restrict__ dst) {
    int i4 = blockIdx.x * 256 + threadIdx.x;
    const int per_batch = STARTI * KDIM / 4;
    const int full_batch = CHART_LEN * KDIM / 4;
    int b = i4 / per_batch;
    int rem = i4 - b * per_batch;
    size_t s = (size_t)b * full_batch + rem;
    dst[s] = src[s];
}

// ---------------------------------------------------------------------------
// bf16 hi/lo split precompute
// ---------------------------------------------------------------------------
__device__ __forceinline__ void split_store(__nv_bfloat16* hi_arr, __nv_bfloat16* lo_arr,
                                            size_t off, float4 v) {
    float vv[4] = {v.x, v.y, v.z, v.w};
    __nv_bfloat16 h[4], l[4];
#pragma unroll
    for (int e = 0; e < 4; e++) {
        h[e] = __float2bfloat16(vv[e]);
        l[e] = __float2bfloat16(vv[e] - __bfloat162float(h[e]));
    }
    __nv_bfloat162 h01 = {h[0], h[1]}, h23 = {h[2], h[3]};
    __nv_bfloat162 l01 = {l[0], l[1]}, l23 = {l[2], l[3]};
    uint2 uh, ul;
    uh.x = *reinterpret_cast<uint32_t*>(&h01); uh.y = *reinterpret_cast<uint32_t*>(&h23);
    ul.x = *reinterpret_cast<uint32_t*>(&l01); ul.y = *reinterpret_cast<uint32_t*>(&l23);
    *reinterpret_cast<uint2*>(hi_arr + off) = uh;
    *reinterpret_cast<uint2*>(lo_arr + off) = ul;
}

__global__ __launch_bounds__(256) void splitA_kernel(const float* __restrict__ chart) {
    size_t i = (size_t)blockIdx.x * 256 + threadIdx.x;
    int x = (int)(i >> 8);
    int k = ((int)i & 255) * 4;
    int bb = x >> 8, op = x & 255;
    float4 v = *(const float4*)(chart + ((size_t)(bb * CHART_LEN + op)) * KDIM + HDIM + k);
    split_store(g_a0, g_a1, (size_t)x * HDIM + k, v);
}

__global__ __launch_bounds__(256) void splitU_kernel(const float* __restrict__ U) {
    size_t i = (size_t)blockIdx.x * 256 + threadIdx.x;
    int c = (int)(i >> 8);
    int k = ((int)i & 255) * 4;
    int side = c / (GATES * HDIM);
    int gj = c - side * (GATES * HDIM);
    float4 v = *(const float4*)(U + (size_t)gj * KDIM + side * HDIM + k);
    split_store(g_u0, g_u1, (size_t)c * HDIM + k, v);
}

// ---------------------------------------------------------------------------
// norm of energy_u (one block)
// ---------------------------------------------------------------------------
__global__ __launch_bounds__(256) void norm_kernel(const float* __restrict__ eu) {
    __shared__ float s_red[8];
    const int tid = threadIdx.x;
    float p = 0.f;
#pragma unroll
    for (int t = 0; t < 4; t++) { float v = eu[tid + t * 256]; p += v * v; }
#pragma unroll
    for (int off = 16; off; off >>= 1) p += __shfl_xor_sync(0xffffffffu, p, off);
    if ((tid & 31) == 0) s_red[tid >> 5] = p;
    __syncthreads();
    if (tid == 0) {
        float s = 0.f;
#pragma unroll
        for (int w = 0; w < 8; w++) s += s_red[w];
        g_unorm = fmaxf(sqrtf(s), 1e-8f);
    }
}

// ---------------------------------------------------------------------------
// K2: HMMA GEMM v2. CTA tile 128x256, warp tile 64x64, BK=32,
// 2-stage cp.async double buffer, 2-split bf16 (3 passes), fp32 accum.
// ---------------------------------------------------------------------------
#define LDSS 40          // halves per smem row (32 data + 8 pad)
#define KT (HDIM / 32)   // 32 chunks
#define ST_A0 0
#define ST_A1 (128 * LDSS)
#define ST_B0 (2 * 128 * LDSS)
#define ST_B1 (2 * 128 * LDSS + 256 * LDSS)
#define STAGE_H (2 * 128 * LDSS + 2 * 256 * LDSS)    // 30720 halves
#define GEMM_SMEM (2 * STAGE_H * 2)                  // 122880 bytes

__global__ __launch_bounds__(256, 1) void mma_gemm_kernel() {
    extern __shared__ __nv_bfloat16 gsm[];
    const uint32_t smem_base = smem_u32(gsm);
    const int tid = threadIdx.x;
    const int wid = tid >> 5, lane = tid & 31;
    const int wm = wid >> 2;        // 0..1
    const int wn = wid & 3;         // 0..3
    const int nbase = blockIdx.x * 256;
    const int xbase = blockIdx.y * 128;

    const int aRow = (lane & 15);
    const int aCol = (lane >> 4) << 4;
    const int bRow = ((lane >> 4) << 3) + (lane & 7);
    const int bCol = ((lane >> 3) & 1) << 4;

    float acc[4][8][4];
#pragma unroll
    for (int mi = 0; mi < 4; mi++)
#pragma unroll
        for (int ni = 0; ni < 8; ni++)
#pragma unroll
            for (int e = 0; e < 4; e++) acc[mi][ni][e] = 0.f;

    // prefetch lambda
    auto prefetch = [&](int kc, int stage) {
        const int kb = kc * 32;
        const uint32_t sbase = smem_base + stage * (STAGE_H * 2);
        // A: 1024 uint4 (2 splits x 128 rows x 4 quads)
#pragma unroll
        for (int it = 0; it < 4; it++) {
            int id = tid + it * 256;
            int split = id >> 9;
            int rem = id & 511;
            int row = rem >> 2, q = rem & 3;
            const __nv_bfloat16* src = (split ? g_a1 : g_a0)
                + (size_t)(xbase + row) * HDIM + kb + q * 8;
            uint32_t dst = sbase + (split ? ST_A1 : ST_A0) * 2 + (row * LDSS + q * 8) * 2;
            cpasync16(dst, src);
        }
        // B: 2048 uint4 (2 splits x 256 rows x 4 quads)
#pragma unroll
        for (int it = 0; it < 8; it++) {
            int id = tid + it * 256;
            int split = id >> 10;
            int rem = id & 1023;
            int row = rem >> 2, q = rem & 3;
            const __nv_bfloat16* src = (split ? g_u1 : g_u0)
                + (size_t)(nbase + row) * HDIM + kb + q * 8;
            uint32_t dst = sbase + (split ? ST_B1 : ST_B0) * 2 + (row * LDSS + q * 8) * 2;
            cpasync16(dst, src);
        }
    };

    prefetch(0, 0);
    CP_COMMIT();

    for (int kc = 0; kc < KT; kc++) {
        if (kc + 1 < KT) {
            prefetch(kc + 1, (kc + 1) & 1);
            CP_COMMIT();
            CP_WAIT1();
        } else {
            CP_WAIT0();
        }
        __syncthreads();

        const uint32_t sb = smem_base + (kc & 1) * (STAGE_H * 2);
        const uint32_t uA0 = sb + ST_A0 * 2, uA1 = sb + ST_A1 * 2;
        const uint32_t uB0 = sb + ST_B0 * 2, uB1 = sb + ST_B1 * 2;

#pragma unroll
        for (int ks = 0; ks < 2; ks++) {
            const int kbytes = ks * 32;
            uint32_t b0f[4][4], b1f[4][4];
#pragma unroll
            for (int nt = 0; nt < 4; nt++) {
                uint32_t off = (uint32_t)((wn * 64 + nt * 16 + bRow) * (LDSS * 2)
                                          + kbytes + bCol);
                LDMATRIX_X4(b0f[nt], uB0 + off);
                LDMATRIX_X4(b1f[nt], uB1 + off);
            }
#pragma unroll
            for (int mi = 0; mi < 4; mi++) {
                uint32_t a0f[4], a1f[4];
                uint32_t off = (uint32_t)((wm * 64 + mi * 16 + aRow) * (LDSS * 2)
                                          + kbytes + aCol);
                LDMATRIX_X4(a0f, uA0 + off);
                LDMATRIX_X4(a1f, uA1 + off);
#pragma unroll
                for (int ni = 0; ni < 8; ni++) {
                    const uint32_t* pb0 = &b0f[ni >> 1][(ni & 1) * 2];
                    const uint32_t* pb1 = &b1f[ni >> 1][(ni & 1) * 2];
                    mma16816(acc[mi][ni], a0f, pb0);
                    mma16816(acc[mi][ni], a0f, pb1);
                    mma16816(acc[mi][ni], a1f, pb0);
                }
            }
        }
        __syncthreads();
    }

    // epilogue
    const int cr = lane >> 2;
    const int cc = (lane & 3) * 2;
#pragma unroll
    for (int mi = 0; mi < 4; mi++) {
        int row0 = xbase + wm * 64 + mi * 16 + cr;
#pragma unroll
        for (int ni = 0; ni < 8; ni++) {
            int col = nbase + wn * 64 + ni * 8 + cc;
            float* p0 = g_p + (size_t)row0 * PPW + col;
            float* p1 = g_p + (size_t)(row0 + 8) * PPW + col;
            *(float2*)p0 = make_float2(acc[mi][ni][0], acc[mi][ni][1]);
            *(float2*)p1 = make_float2(acc[mi][ni][2], acc[mi][ni][3]);
        }
    }
}

// ---------------------------------------------------------------------------
// K3: fused gates + softmax-combine. One block per (step, batch).
// c,h stored in fp16 smem (energy uses fp32 h before rounding).
// ---------------------------------------------------------------------------
#define FSM_C   0
#define FSM_H   65536
#define FSM_WSE 131072
#define FSM_WS2 (FSM_WSE + 2048)
#define FSM_W   (FSM_WS2 + 2048)
#define FSM_OPS (FSM_W + 128)
#define FSM_TOTAL (FSM_OPS + 256)

__global__ __launch_bounds__(512) void fused_kernel(
    const float* __restrict__ chart, const int* __restrict__ ops,
    const float* __restrict__ bias, const float* __restrict__ eu,
    float* __restrict__ out)
{
    extern __shared__ char fsm[];
    __half2* s_c = (__half2*)(fsm + FSM_C);     // [32][512]
    __half2* s_h = (__half2*)(fsm + FSM_H);
    float* s_wse = (float*)(fsm + FSM_WSE);     // [32][16]
    float* s_ws2 = (float*)(fsm + FSM_WS2);
    float* s_w   = (float*)(fsm + FSM_W);       // [32]
    int*   s_ops = (int*)(fsm + FSM_OPS);       // [64]

    const int tid = threadIdx.x;
    const int warp = tid >> 5, lane = tid & 31;
    const int sbid = blockIdx.x;                // ordered (b, step) for PP L2 locality
    const int bb = sbid >> 7;
    const int step = sbid & 127;

    if (tid < 64) s_ops[tid] = ops[(size_t)((step * BSZ + bb) * AMB) * 2 + tid];
    __syncthreads();

    const float2 eu2 = ((const float2*)eu)[tid];
    float2 bi2[GATES];
#pragma unroll
    for (int g = 0; g < GATES; g++) bi2[g] = ((const float2*)bias)[g * 512 + tid];

#pragma unroll 1
    for (int a = 0; a < AMB; a++) {
        const int opL = s_ops[2 * a];
        const int opR = s_ops[2 * a + 1];
        const float2* pL = (const float2*)(g_p + (size_t)(bb * STARTI + opL) * PPW);
        const float2* pR = (const float2*)(g_p + (size_t)(bb * STARTI + opR) * PPW
                                           + GATES * HDIM);
        const float2 ccl = ((const float2*)(chart + (size_t)(bb * CHART_LEN + opL) * KDIM))[tid];
        const float2 ccr = ((const float2*)(chart + (size_t)(bb * CHART_LEN + opR) * KDIM))[tid];

        float2 pv[GATES];
#pragma unroll
        for (int g = 0; g < GATES; g++) {
            float2 l = pL[g * 512 + tid];
            float2 r = pR[g * 512 + tid];
            pv[g] = make_float2(l.x + r.x + bi2[g].x, l.y + r.y + bi2[g].y);
        }
        float c0, c1, h0, h1;
        {
            float ig = sigmoidf_(pv[0].x), fl = sigmoidf_(pv[1].x);
            float fr = sigmoidf_(pv[2].x), og = sigmoidf_(pv[3].x);
            float ut = tanhf(pv[4].x);
            c0 = fl * ccl.x + fr * ccr.x + ig * ut;
            h0 = og * tanhf(c0);
        }
        {
            float ig = sigmoidf_(pv[0].y), fl = sigmoidf_(pv[1].y);
            float fr = sigmoidf_(pv[2].y), og = sigmoidf_(pv[3].y);
            float ut = tanhf(pv[4].y);
            c1 = fl * ccl.y + fr * ccr.y + ig * ut;
            h1 = og * tanhf(c1);
        }
        s_c[a * 512 + tid] = __floats2half2_rn(c0, c1);
        s_h[a * 512 + tid] = __floats2half2_rn(h0, h1);

        float se = h0 * eu2.x + h1 * eu2.y;
        float s2 = h0 * h0 + h1 * h1;
#pragma unroll
        for (int off = 16; off; off >>= 1) {
            se += __shfl_xor_sync(0xffffffffu, se, off);
            s2 += __shfl_xor_sync(0xffffffffu, s2, off);
        }
        if (lane == 0) { s_wse[a * 16 + warp] = se; s_ws2[a * 16 + warp] = s2; }
    }
    __syncthreads();

    if (tid < 32) {
        float se = 0.f, s2 = 0.f;
#pragma unroll
        for (int w = 0; w < 16; w++) { se += s_wse[tid * 16 + w]; s2 += s_ws2[tid * 16 + w]; }
        float hn = fmaxf(sqrtf(s2), 1e-8f);
        float e = se / (g_unorm * hn);
        float m = e;
#pragma unroll
        for (int off = 16; off; off >>= 1) m = fmaxf(m, __shfl_xor_sync(0xffffffffu, m, off));
        float p = __expf(e - m);
        float s = p;
#pragma unroll
        for (int off = 16; off; off >>= 1) s += __shfl_xor_sync(0xffffffffu, s, off);
        s_w[tid] = p / s;
    }
    __syncthreads();

    float ac0 = 0.f, ac1 = 0.f, ah0 = 0.f, ah1 = 0.f;
#pragma unroll
    for (int a = 0; a < AMB; a++) {
        float w = s_w[a];
        float2 cv = __half22float2(s_c[a * 512 + tid]);
        float2 hv = __half22float2(s_h[a * 512 + tid]);
        ac0 += w * cv.x; ac1 += w * cv.y;
        ah0 += w * hv.x; ah1 += w * hv.y;
    }
    float* orow = out + ((size_t)bb * CHART_LEN + (STARTI + step)) * KDIM;
    ((float2*)orow)[tid] = make_float2(ac0, ac1);
    ((float2*)(orow + HDIM))[tid] = make_float2(ah0, ah1);
}

// ---------------------------------------------------------------------------
extern "C" void kernel_launch(void* const* d_in, const int* in_sizes, int n_in,
                              void* d_out, int out_size) {
    const float* chart = (const float*)d_in[0];
    const int*   ops   = (const int*)d_in[1];
    const float* U     = (const float*)d_in[3];
    const float* bias  = (const float*)d_in[4];
    const float* eu    = (const float*)d_in[5];
    float* out = (float*)d_out;

    cudaFuncSetAttribute(mma_gemm_kernel,
                         cudaFuncAttributeMaxDynamicSharedMemorySize, GEMM_SMEM);
    cudaFuncSetAttribute(fused_kernel,
                         cudaFuncAttributeMaxDynamicSharedMemorySize, FSM_TOTAL);

    const int n4 = BSZ * STARTI * KDIM / 4;
    copy_kernel<<<n4 / 256, 256>>>((const float4*)chart, (float4*)out);

    splitA_kernel<<<NX, 256>>>(chart);
    splitU_kernel<<<PPW, 256>>>(U);
    norm_kernel<<<1, 256>>>(eu);

    dim3 g2(PPW / 256, NX / 128);   // (40, 64)
    mma_gemm_kernel<<<g2, 256, GEMM_SMEM>>>();

    fused_kernel<<<STEPS * BSZ, 512, FSM_TOTAL>>>(chart, ops, bias, eu, out);
}

// round 6
// speedup vs baseline: 1.1056x; 1.1056x over previous
#include <cuda_runtime.h>
#include <cuda_bf16.h>
#include <cuda_fp16.h>
#include <math.h>
#include <cstdint>

// Problem constants
#define HDIM 1024
#define KDIM 2048
#define GATES 5
#define BSZ 32
#define STEPS 128
#define AMB 32
#define STARTI 256
#define CHART_LEN 384
#define NROWS (STEPS * BSZ * AMB)   // 131072
#define NX (BSZ * STARTI)           // 8192
#define PPW (2 * GATES * HDIM)      // 10240

// Static device scratch
__device__ float g_p[(size_t)NX * PPW];
__device__ __nv_bfloat16 g_a0[(size_t)NX * HDIM];
__device__ __nv_bfloat16 g_a1[(size_t)NX * HDIM];
__device__ __nv_bfloat16 g_u0[(size_t)PPW * HDIM];
__device__ __nv_bfloat16 g_u1[(size_t)PPW * HDIM];
__device__ __half2 g_c16[(size_t)NROWS * (HDIM / 2)];
__device__ __half2 g_h16[(size_t)NROWS * (HDIM / 2)];
__device__ float g_se[NROWS];
__device__ float g_s2[NROWS];
__device__ float g_unorm;

__device__ __forceinline__ float sigmoidf_(float x) {
    return 1.0f / (1.0f + __expf(-x));
}
__device__ __forceinline__ uint32_t smem_u32(const void* p) {
    uint32_t a;
    asm("{ .reg .u64 t; cvta.to.shared.u64 t, %1; cvt.u32.u64 %0, t; }" : "=r"(a) : "l"(p));
    return a;
}
#define LDMATRIX_X4(r, addr) \
    asm volatile("ldmatrix.sync.aligned.m8n8.x4.shared.b16 {%0,%1,%2,%3}, [%4];" \
        : "=r"((r)[0]), "=r"((r)[1]), "=r"((r)[2]), "=r"((r)[3]) : "r"(addr))
__device__ __forceinline__ void mma16816(float* d, const uint32_t* a, const uint32_t* b) {
    asm volatile(
        "mma.sync.aligned.m16n8k16.row.col.f32.bf16.bf16.f32 "
        "{%0,%1,%2,%3}, {%4,%5,%6,%7}, {%8,%9}, {%0,%1,%2,%3};"
        : "+f"(d[0]), "+f"(d[1]), "+f"(d[2]), "+f"(d[3])
        : "r"(a[0]), "r"(a[1]), "r"(a[2]), "r"(a[3]), "r"(b[0]), "r"(b[1]));
}
__device__ __forceinline__ void cpasync16(uint32_t dst, const __nv_bfloat16* src) {
    asm volatile("cp.async.cg.shared.global [%0], [%1], 16;"
        :: "r"(dst), "l"((size_t)__cvta_generic_to_global(src)));
}
#define CP_COMMIT() asm volatile("cp.async.commit_group;" ::: "memory")
#define CP_WAIT1()  asm volatile("cp.async.wait_group 1;" ::: "memory")
#define CP_WAIT0()  asm volatile("cp.async.wait_group 0;" ::: "memory")

// ---------------------------------------------------------------------------
// K1: copy chart rows [0,256)
// ---------------------------------------------------------------------------
__global__ __launch_bounds__(256) void copy_kernel(const float4* __restrict__ src,
                                                   float4* __restrict__ dst) {
    int i4 = blockIdx.x * 256 + threadIdx.x;
    const int per_batch = STARTI * KDIM / 4;
    const int full_batch = CHART_LEN * KDIM / 4;
    int b = i4 / per_batch;
    int rem = i4 - b * per_batch;
    size_t s = (size_t)b * full_batch + rem;
    dst[s] = src[s];
}

// ---------------------------------------------------------------------------
// bf16 hi/lo split precompute
// ---------------------------------------------------------------------------
__device__ __forceinline__ void split_store(__nv_bfloat16* hi_arr, __nv_bfloat16* lo_arr,
                                            size_t off, float4 v) {
    float vv[4] = {v.x, v.y, v.z, v.w};
    __nv_bfloat16 h[4], l[4];
#pragma unroll
    for (int e = 0; e < 4; e++) {
        h[e] = __float2bfloat16(vv[e]);
        l[e] = __float2bfloat16(vv[e] - __bfloat162float(h[e]));
    }
    __nv_bfloat162 h01 = {h[0], h[1]}, h23 = {h[2], h[3]};
    __nv_bfloat162 l01 = {l[0], l[1]}, l23 = {l[2], l[3]};
    uint2 uh, ul;
    uh.x = *reinterpret_cast<uint32_t*>(&h01); uh.y = *reinterpret_cast<uint32_t*>(&h23);
    ul.x = *reinterpret_cast<uint32_t*>(&l01); ul.y = *reinterpret_cast<uint32_t*>(&l23);
    *reinterpret_cast<uint2*>(hi_arr + off) = uh;
    *reinterpret_cast<uint2*>(lo_arr + off) = ul;
}

__global__ __launch_bounds__(256) void splitA_kernel(const float* __restrict__ chart) {
    size_t i = (size_t)blockIdx.x * 256 + threadIdx.x;
    int x = (int)(i >> 8);
    int k = ((int)i & 255) * 4;
    int bb = x >> 8, op = x & 255;
    float4 v = *(const float4*)(chart + ((size_t)(bb * CHART_LEN + op)) * KDIM + HDIM + k);
    split_store(g_a0, g_a1, (size_t)x * HDIM + k, v);
}

__global__ __launch_bounds__(256) void splitU_kernel(const float* __restrict__ U) {
    size_t i = (size_t)blockIdx.x * 256 + threadIdx.x;
    int c = (int)(i >> 8);
    int k = ((int)i & 255) * 4;
    int side = c / (GATES * HDIM);
    int gj = c - side * (GATES * HDIM);
    float4 v = *(const float4*)(U + (size_t)gj * KDIM + side * HDIM + k);
    split_store(g_u0, g_u1, (size_t)c * HDIM + k, v);
}

// ---------------------------------------------------------------------------
// norm of energy_u
// ---------------------------------------------------------------------------
__global__ __launch_bounds__(256) void norm_kernel(const float* __restrict__ eu) {
    __shared__ float s_red[8];
    const int tid = threadIdx.x;
    float p = 0.f;
#pragma unroll
    for (int t = 0; t < 4; t++) { float v = eu[tid + t * 256]; p += v * v; }
#pragma unroll
    for (int off = 16; off; off >>= 1) p += __shfl_xor_sync(0xffffffffu, p, off);
    if ((tid & 31) == 0) s_red[tid >> 5] = p;
    __syncthreads();
    if (tid == 0) {
        float s = 0.f;
#pragma unroll
        for (int w = 0; w < 8; w++) s += s_red[w];
        g_unorm = fmaxf(sqrtf(s), 1e-8f);
    }
}

// ---------------------------------------------------------------------------
// K2: HMMA GEMM (R5 structure). CTA 128x256, warp 64x64, BK=32,
// 2-stage cp.async, 2-split bf16 (3 passes), fp32 accum.
// ---------------------------------------------------------------------------
#define LDSS 40
#define KT (HDIM / 32)
#define ST_A0 0
#define ST_A1 (128 * LDSS)
#define ST_B0 (2 * 128 * LDSS)
#define ST_B1 (2 * 128 * LDSS + 256 * LDSS)
#define STAGE_H (2 * 128 * LDSS + 2 * 256 * LDSS)
#define GEMM_SMEM (2 * STAGE_H * 2)

__global__ __launch_bounds__(256, 1) void mma_gemm_kernel() {
    extern __shared__ __nv_bfloat16 gsm[];
    const uint32_t smem_base = smem_u32(gsm);
    const int tid = threadIdx.x;
    const int wid = tid >> 5, lane = tid & 31;
    const int wm = wid >> 2;
    const int wn = wid & 3;
    const int nbase = blockIdx.x * 256;
    const int xbase = blockIdx.y * 128;

    const int aRow = (lane & 15);
    const int aCol = (lane >> 4) << 4;
    const int bRow = ((lane >> 4) << 3) + (lane & 7);
    const int bCol = ((lane >> 3) & 1) << 4;

    float acc[4][8][4];
#pragma unroll
    for (int mi = 0; mi < 4; mi++)
#pragma unroll
        for (int ni = 0; ni < 8; ni++)
#pragma unroll
            for (int e = 0; e < 4; e++) acc[mi][ni][e] = 0.f;

    auto prefetch = [&](int kc, int stage) {
        const int kb = kc * 32;
        const uint32_t sbase = smem_base + stage * (STAGE_H * 2);
#pragma unroll
        for (int it = 0; it < 4; it++) {
            int id = tid + it * 256;
            int split = id >> 9;
            int rem = id & 511;
            int row = rem >> 2, q = rem & 3;
            const __nv_bfloat16* src = (split ? g_a1 : g_a0)
                + (size_t)(xbase + row) * HDIM + kb + q * 8;
            uint32_t dst = sbase + (split ? ST_A1 : ST_A0) * 2 + (row * LDSS + q * 8) * 2;
            cpasync16(dst, src);
        }
#pragma unroll
        for (int it = 0; it < 8; it++) {
            int id = tid + it * 256;
            int split = id >> 10;
            int rem = id & 1023;
            int row = rem >> 2, q = rem & 3;
            const __nv_bfloat16* src = (split ? g_u1 : g_u0)
                + (size_t)(nbase + row) * HDIM + kb + q * 8;
            uint32_t dst = sbase + (split ? ST_B1 : ST_B0) * 2 + (row * LDSS + q * 8) * 2;
            cpasync16(dst, src);
        }
    };

    prefetch(0, 0);
    CP_COMMIT();

    for (int kc = 0; kc < KT; kc++) {
        if (kc + 1 < KT) {
            prefetch(kc + 1, (kc + 1) & 1);
            CP_COMMIT();
            CP_WAIT1();
        } else {
            CP_WAIT0();
        }
        __syncthreads();

        const uint32_t sb = smem_base + (kc & 1) * (STAGE_H * 2);
        const uint32_t uA0 = sb + ST_A0 * 2, uA1 = sb + ST_A1 * 2;
        const uint32_t uB0 = sb + ST_B0 * 2, uB1 = sb + ST_B1 * 2;

#pragma unroll
        for (int ks = 0; ks < 2; ks++) {
            const int kbytes = ks * 32;
            uint32_t b0f[4][4], b1f[4][4];
#pragma unroll
            for (int nt = 0; nt < 4; nt++) {
                uint32_t off = (uint32_t)((wn * 64 + nt * 16 + bRow) * (LDSS * 2)
                                          + kbytes + bCol);
                LDMATRIX_X4(b0f[nt], uB0 + off);
                LDMATRIX_X4(b1f[nt], uB1 + off);
            }
#pragma unroll
            for (int mi = 0; mi < 4; mi++) {
                uint32_t a0f[4], a1f[4];
                uint32_t off = (uint32_t)((wm * 64 + mi * 16 + aRow) * (LDSS * 2)
                                          + kbytes + aCol);
                LDMATRIX_X4(a0f, uA0 + off);
                LDMATRIX_X4(a1f, uA1 + off);
#pragma unroll
                for (int ni = 0; ni < 8; ni++) {
                    const uint32_t* pb0 = &b0f[ni >> 1][(ni & 1) * 2];
                    const uint32_t* pb1 = &b1f[ni >> 1][(ni & 1) * 2];
                    mma16816(acc[mi][ni], a0f, pb0);
                    mma16816(acc[mi][ni], a0f, pb1);
                    mma16816(acc[mi][ni], a1f, pb0);
                }
            }
        }
        __syncthreads();
    }

    const int cr = lane >> 2;
    const int cc = (lane & 3) * 2;
#pragma unroll
    for (int mi = 0; mi < 4; mi++) {
        int row0 = xbase + wm * 64 + mi * 16 + cr;
#pragma unroll
        for (int ni = 0; ni < 8; ni++) {
            int col = nbase + wn * 64 + ni * 8 + cc;
            float* p0 = g_p + (size_t)row0 * PPW + col;
            float* p1 = g_p + (size_t)(row0 + 8) * PPW + col;
            *(float2*)p0 = make_float2(acc[mi][ni][0], acc[mi][ni][1]);
            *(float2*)p1 = make_float2(acc[mi][ni][2], acc[mi][ni][3]);
        }
    }
}

// ---------------------------------------------------------------------------
// K3: gather-add preacts + gates -> fp16 c,h + per-row energy stats (fp32 h).
// Blocks ordered (b, step, a) for PP L2 locality.
// ---------------------------------------------------------------------------
__global__ __launch_bounds__(256) void gates_kernel(
    const float* __restrict__ chart, const int* __restrict__ ops,
    const float* __restrict__ bias, const float* __restrict__ eu)
{
    __shared__ float s_se[8], s_s2[8];

    const int bid = blockIdx.x;
    const int bb = bid >> 12;
    const int rem = bid & 4095;
    const size_t r = (size_t)(rem >> 5) * (BSZ * AMB) + bb * AMB + (rem & 31);

    const int opL = ops[2 * r];
    const int opR = ops[2 * r + 1];
    const int xL = bb * STARTI + opL;
    const int xR = bb * STARTI + opR;

    const float4* pL = (const float4*)(g_p + (size_t)xL * PPW);
    const float4* pR = (const float4*)(g_p + (size_t)xR * PPW + GATES * HDIM);
    const float4* cL = (const float4*)(chart + (size_t)(bb * CHART_LEN + opL) * KDIM);
    const float4* cR = (const float4*)(chart + (size_t)(bb * CHART_LEN + opR) * KDIM);
    const float4* b4 = (const float4*)bias;

    const int tid = threadIdx.x;
    const int j4 = tid;
    const int q = HDIM / 4;

    float4 vi = pL[0 * q + j4], vfl = pL[1 * q + j4], vfr = pL[2 * q + j4];
    float4 vo = pL[3 * q + j4], vu = pL[4 * q + j4];
    float4 wi = pR[0 * q + j4], wfl = pR[1 * q + j4], wfr = pR[2 * q + j4];
    float4 wo = pR[3 * q + j4], wu = pR[4 * q + j4];
    float4 bi = b4[0 * q + j4], bfl = b4[1 * q + j4], bfr = b4[2 * q + j4];
    float4 bo = b4[3 * q + j4], bu = b4[4 * q + j4];
    float4 ccl = cL[j4], ccr = cR[j4];
    float4 eu4 = ((const float4*)eu)[j4];

    float pi[4] = {vi.x + wi.x + bi.x, vi.y + wi.y + bi.y, vi.z + wi.z + bi.z, vi.w + wi.w + bi.w};
    float pf[4] = {vfl.x + wfl.x + bfl.x, vfl.y + wfl.y + bfl.y, vfl.z + wfl.z + bfl.z, vfl.w + wfl.w + bfl.w};
    float pg[4] = {vfr.x + wfr.x + bfr.x, vfr.y + wfr.y + bfr.y, vfr.z + wfr.z + bfr.z, vfr.w + wfr.w + bfr.w};
    float po[4] = {vo.x + wo.x + bo.x, vo.y + wo.y + bo.y, vo.z + wo.z + bo.z, vo.w + wo.w + bo.w};
    float pu[4] = {vu.x + wu.x + bu.x, vu.y + wu.y + bu.y, vu.z + wu.z + bu.z, vu.w + wu.w + bu.w};
    float l[4] = {ccl.x, ccl.y, ccl.z, ccl.w};
    float rr[4] = {ccr.x, ccr.y, ccr.z, ccr.w};
    float ev[4] = {eu4.x, eu4.y, eu4.z, eu4.w};
    float c[4], h[4];
    float se = 0.f, s2 = 0.f;
#pragma unroll
    for (int e = 0; e < 4; e++) {
        float ig = sigmoidf_(pi[e]);
        float fl = sigmoidf_(pf[e]);
        float fr = sigmoidf_(pg[e]);
        float og = sigmoidf_(po[e]);
        float ut = tanhf(pu[e]);
        c[e] = fl * l[e] + fr * rr[e] + ig * ut;
        h[e] = og * tanhf(c[e]);
        se += h[e] * ev[e];
        s2 += h[e] * h[e];
    }
    __half2* oc = g_c16 + r * (HDIM / 2) + j4 * 2;
    __half2* oh = g_h16 + r * (HDIM / 2) + j4 * 2;
    oc[0] = __floats2half2_rn(c[0], c[1]);
    oc[1] = __floats2half2_rn(c[2], c[3]);
    oh[0] = __floats2half2_rn(h[0], h[1]);
    oh[1] = __floats2half2_rn(h[2], h[3]);

#pragma unroll
    for (int off = 16; off; off >>= 1) {
        se += __shfl_xor_sync(0xffffffffu, se, off);
        s2 += __shfl_xor_sync(0xffffffffu, s2, off);
    }
    if ((tid & 31) == 0) { s_se[tid >> 5] = se; s_s2[tid >> 5] = s2; }
    __syncthreads();
    if (tid == 0) {
        float a = 0.f, b = 0.f;
#pragma unroll
        for (int w = 0; w < 8; w++) { a += s_se[w]; b += s_s2[w]; }
        g_se[r] = a;
        g_s2[r] = b;
    }
}

// ---------------------------------------------------------------------------
// K4: softmax from precomputed stats + fp16 weighted combine.
// ---------------------------------------------------------------------------
__global__ __launch_bounds__(256) void combine_kernel(float* __restrict__ out) {
    __shared__ float s_w[AMB];

    const int tid = threadIdx.x;
    const int sb = blockIdx.x;
    const int step = sb >> 5;
    const int bb = sb & 31;
    const size_t rbase = (size_t)sb * AMB;

    if (tid < 32) {
        float se = g_se[rbase + tid];
        float s2 = g_s2[rbase + tid];
        float hn = fmaxf(sqrtf(s2), 1e-8f);
        float e = se / (g_unorm * hn);
        float m = e;
#pragma unroll
        for (int off = 16; off; off >>= 1) m = fmaxf(m, __shfl_xor_sync(0xffffffffu, m, off));
        float p = __expf(e - m);
        float s = p;
#pragma unroll
        for (int off = 16; off; off >>= 1) s += __shfl_xor_sync(0xffffffffu, s, off);
        s_w[tid] = p / s;
    }
    __syncthreads();

    float ac[4] = {0.f, 0.f, 0.f, 0.f};
    float ah[4] = {0.f, 0.f, 0.f, 0.f};
    const size_t cbase = rbase * (HDIM / 2) + tid * 2;
#pragma unroll 4
    for (int a = 0; a < AMB; a++) {
        float w = s_w[a];
        uint2 cv = *(const uint2*)(g_c16 + cbase + (size_t)a * (HDIM / 2));
        uint2 hv = *(const uint2*)(g_h16 + cbase + (size_t)a * (HDIM / 2));
        float2 c0 = __half22float2(*(__half2*)&cv.x);
        float2 c1 = __half22float2(*(__half2*)&cv.y);
        float2 h0 = __half22float2(*(__half2*)&hv.x);
        float2 h1 = __half22float2(*(__half2*)&hv.y);
        ac[0] += w * c0.x; ac[1] += w * c0.y; ac[2] += w * c1.x; ac[3] += w * c1.y;
        ah[0] += w * h0.x; ah[1] += w * h0.y; ah[2] += w * h1.x; ah[3] += w * h1.y;
    }
    float* orow = out + ((size_t)bb * CHART_LEN + (STARTI + step)) * KDIM;
    ((float4*)orow)[tid] = make_float4(ac[0], ac[1], ac[2], ac[3]);
    ((float4*)(orow + HDIM))[tid] = make_float4(ah[0], ah[1], ah[2], ah[3]);
}

// ---------------------------------------------------------------------------
extern "C" void kernel_launch(void* const* d_in, const int* in_sizes, int n_in,
                              void* d_out, int out_size) {
    const float* chart = (const float*)d_in[0];
    const int*   ops   = (const int*)d_in[1];
    const float* U     = (const float*)d_in[3];
    const float* bias  = (const float*)d_in[4];
    const float* eu    = (const float*)d_in[5];
    float* out = (float*)d_out;

    cudaFuncSetAttribute(mma_gemm_kernel,
                         cudaFuncAttributeMaxDynamicSharedMemorySize, GEMM_SMEM);

    const int n4 = BSZ * STARTI * KDIM / 4;
    copy_kernel<<<n4 / 256, 256>>>((const float4*)chart, (float4*)out);

    splitA_kernel<<<NX, 256>>>(chart);
    splitU_kernel<<<PPW, 256>>>(U);
    norm_kernel<<<1, 256>>>(eu);

    dim3 g2(PPW / 256, NX / 128);   // (40, 64)
    mma_gemm_kernel<<<g2, 256, GEMM_SMEM>>>();

    gates_kernel<<<NROWS, 256>>>(chart, ops, bias, eu);

    combine_kernel<<<STEPS * BSZ, 256>>>(out);
}